// round 2
// baseline (speedup 1.0000x reference)
#include <cuda_runtime.h>

// Fused LatentDynamicsModel:
//   x      = relu([z|a] @ W_in^T + b_in)
//   gi     = x @ W_ih^T + b_ih ; gh = h @ W_hh^T + b_hh   (gates r,z,n)
//   r      = sigmoid(i_r + h_r); zg = sigmoid(i_z + h_z)
//   n      = tanh(i_n + r * h_n)
//   h_new  = (1-zg)*n + zg*h
//   y      = relu(h_new @ W_o1^T + b_o1)
//   z_next = y @ W_o2^T + b_o2
// Output layout: d_out[0 : B*64) = z_next, d_out[B*64 : B*64+B*256) = h_new.

#define HID     256
#define LATENT  64
#define ACT     2
#define TM      32      // rows per CTA
#define THREADS 256

// SMEM float counts
#define ZA_LD   96                 // padded K for input projection (66 real)
#define WST_LD  257                // transposed weight tile leading dim

__device__ __forceinline__ float sigmoidf_(float x) {
    return 1.0f / (1.0f + __expf(-x));
}

// Accumulate acc[4][NJ] += As[TM x K] @ W^T chunk.
// W: row-major [N rows, ldw cols], N = NJ*32 rows used.
// As: smem, lda stride. K covered in tiles of 32 (Ktiles tiles), zero-padded
// beyond Kreal (As must be zero-padded to Ktiles*32 columns as well).
// Thread mapping: c = lane (0..31), rg4 = 4*(warp id) -> rows rg4..rg4+3,
// cols n = c + 32*j.
template <int NJ>
__device__ __forceinline__ void gemm_acc(
    float acc[4][NJ],
    const float* __restrict__ W, int ldw, int Kreal, int Ktiles,
    const float* __restrict__ As, int lda,
    float* __restrict__ Wst, int tid, int c, int rg4)
{
    for (int t = 0; t < Ktiles; ++t) {
        const int k0 = t * 32;
        // Cooperative transposed load of W tile [32 k x NJ*32 n] -> Wst[kk][n]
        #pragma unroll
        for (int i = 0; i < NJ; ++i) {
            int id  = tid + THREADS * i;      // [0, NJ*256)
            int kk4 = (id & 7) * 4;           // k offset within tile (x4)
            int n   = id >> 3;                // weight row
            int kb  = k0 + kk4;
            const float* wp = W + (long)n * ldw + kb;
            float v0 = (kb + 0 < Kreal) ? wp[0] : 0.0f;
            float v1 = (kb + 1 < Kreal) ? wp[1] : 0.0f;
            float v2 = (kb + 2 < Kreal) ? wp[2] : 0.0f;
            float v3 = (kb + 3 < Kreal) ? wp[3] : 0.0f;
            Wst[(kk4 + 0) * WST_LD + n] = v0;
            Wst[(kk4 + 1) * WST_LD + n] = v1;
            Wst[(kk4 + 2) * WST_LD + n] = v2;
            Wst[(kk4 + 3) * WST_LD + n] = v3;
        }
        __syncthreads();

        const float* a0p = As + (rg4 + 0) * lda + k0;
        const float* a1p = As + (rg4 + 1) * lda + k0;
        const float* a2p = As + (rg4 + 2) * lda + k0;
        const float* a3p = As + (rg4 + 3) * lda + k0;
        #pragma unroll 8
        for (int kk = 0; kk < 32; ++kk) {
            float a0 = a0p[kk];   // warp-uniform (broadcast)
            float a1 = a1p[kk];
            float a2 = a2p[kk];
            float a3 = a3p[kk];
            const float* wrow = Wst + kk * WST_LD + c;
            #pragma unroll
            for (int j = 0; j < NJ; ++j) {
                float w = wrow[32 * j];       // lane-consecutive: conflict-free
                acc[0][j] += a0 * w;
                acc[1][j] += a1 * w;
                acc[2][j] += a2 * w;
                acc[3][j] += a3 * w;
            }
        }
        __syncthreads();
    }
}

__global__ __launch_bounds__(THREADS, 1)
void latent_dynamics_kernel(
    const float* __restrict__ z,
    const float* __restrict__ action,
    const float* __restrict__ hidden,
    const float* __restrict__ W_in,  const float* __restrict__ b_in,
    const float* __restrict__ W_ih,  const float* __restrict__ W_hh,
    const float* __restrict__ b_ih,  const float* __restrict__ b_hh,
    const float* __restrict__ W_o1,  const float* __restrict__ b_o1,
    const float* __restrict__ W_o2,  const float* __restrict__ b_o2,
    float* __restrict__ out_z,       // [B, 64]
    float* __restrict__ out_h)       // [B, 256]
{
    extern __shared__ float smem[];
    float* As_x = smem;                      // TM*HID     = 8192
    float* As_h = As_x + TM * HID;           // TM*HID     = 8192
    float* HN   = As_h + TM * HID;           // TM*HID     = 8192
    float* za   = HN   + TM * HID;           // TM*ZA_LD   = 3072
    float* Wst  = za   + TM * ZA_LD;         // 32*WST_LD  = 8224

    const int tid  = threadIdx.x;
    const int c    = tid & 31;          // lane
    const int rg4  = (tid >> 5) * 4;    // first of 4 rows this thread owns
    const long row0 = (long)blockIdx.x * TM;

    // ---- load inputs: za = [z | action | 0-pad], As_h = h tile ----
    for (int id = tid; id < TM * ZA_LD; id += THREADS) {
        int r = id / ZA_LD, cc = id - r * ZA_LD;
        float v = 0.0f;
        long gr = row0 + r;
        if (cc < LATENT)            v = z[gr * LATENT + cc];
        else if (cc < LATENT + ACT) v = action[gr * ACT + (cc - LATENT)];
        za[id] = v;
    }
    for (int id = tid; id < TM * HID; id += THREADS) {
        int r = id >> 8, cc = id & 255;
        As_h[id] = hidden[(row0 + r) * HID + cc];
    }
    __syncthreads();

    float acc[4][8];

    // ---- P0: x = relu([z|a] @ W_in^T + b_in) ----
    #pragma unroll
    for (int i = 0; i < 4; ++i)
        #pragma unroll
        for (int j = 0; j < 8; ++j) acc[i][j] = 0.0f;
    gemm_acc<8>(acc, W_in, LATENT + ACT, LATENT + ACT, 3, za, ZA_LD, Wst, tid, c, rg4);
    #pragma unroll
    for (int j = 0; j < 8; ++j) {
        int n = c + 32 * j;
        float b = b_in[n];
        #pragma unroll
        for (int i = 0; i < 4; ++i)
            As_x[(rg4 + i) * HID + n] = fmaxf(acc[i][j] + b, 0.0f);
    }
    __syncthreads();

    // ---- P1: HN = h @ W_hh_n^T + b_hh_n ----
    #pragma unroll
    for (int i = 0; i < 4; ++i)
        #pragma unroll
        for (int j = 0; j < 8; ++j) acc[i][j] = 0.0f;
    gemm_acc<8>(acc, W_hh + 2 * HID * HID, HID, HID, 8, As_h, HID, Wst, tid, c, rg4);
    #pragma unroll
    for (int j = 0; j < 8; ++j) {
        int n = c + 32 * j;
        float b = b_hh[2 * HID + n];
        #pragma unroll
        for (int i = 0; i < 4; ++i)
            HN[(rg4 + i) * HID + n] = acc[i][j] + b;
    }
    // no sync needed: HN elements are thread-private across P1..P4

    // ---- P2: r = sigmoid(x@W_ih_r^T + h@W_hh_r^T + b); HN *= r ----
    #pragma unroll
    for (int i = 0; i < 4; ++i)
        #pragma unroll
        for (int j = 0; j < 8; ++j) acc[i][j] = 0.0f;
    gemm_acc<8>(acc, W_ih, HID, HID, 8, As_x, HID, Wst, tid, c, rg4);
    gemm_acc<8>(acc, W_hh, HID, HID, 8, As_h, HID, Wst, tid, c, rg4);
    #pragma unroll
    for (int j = 0; j < 8; ++j) {
        int n = c + 32 * j;
        float b = b_ih[n] + b_hh[n];
        #pragma unroll
        for (int i = 0; i < 4; ++i) {
            float r = sigmoidf_(acc[i][j] + b);
            HN[(rg4 + i) * HID + n] *= r;
        }
    }

    // ---- P3: n = tanh(x@W_ih_n^T + b_ih_n + r*h_n); HN = n ----
    #pragma unroll
    for (int i = 0; i < 4; ++i)
        #pragma unroll
        for (int j = 0; j < 8; ++j) acc[i][j] = 0.0f;
    gemm_acc<8>(acc, W_ih + 2 * HID * HID, HID, HID, 8, As_x, HID, Wst, tid, c, rg4);
    #pragma unroll
    for (int j = 0; j < 8; ++j) {
        int n = c + 32 * j;
        float b = b_ih[2 * HID + n];
        #pragma unroll
        for (int i = 0; i < 4; ++i) {
            int idx = (rg4 + i) * HID + n;
            HN[idx] = tanhf(acc[i][j] + b + HN[idx]);
        }
    }

    // ---- P4: zg = sigmoid(x@W_ih_z^T + h@W_hh_z^T + b); h_new ----
    #pragma unroll
    for (int i = 0; i < 4; ++i)
        #pragma unroll
        for (int j = 0; j < 8; ++j) acc[i][j] = 0.0f;
    gemm_acc<8>(acc, W_ih + 1 * HID * HID, HID, HID, 8, As_x, HID, Wst, tid, c, rg4);
    gemm_acc<8>(acc, W_hh + 1 * HID * HID, HID, HID, 8, As_h, HID, Wst, tid, c, rg4);
    #pragma unroll
    for (int j = 0; j < 8; ++j) {
        int n = c + 32 * j;
        float b = b_ih[HID + n] + b_hh[HID + n];
        #pragma unroll
        for (int i = 0; i < 4; ++i) {
            int idx = (rg4 + i) * HID + n;
            float zg    = sigmoidf_(acc[i][j] + b);
            float hprev = As_h[idx];
            float hnew  = (1.0f - zg) * HN[idx] + zg * hprev;
            out_h[(row0 + rg4 + i) * HID + n] = hnew;
            As_x[idx] = hnew;   // reuse As_x as h_new for the output head
        }
    }
    __syncthreads();

    // ---- P5: y = relu(h_new @ W_o1^T + b_o1) -> As_h ----
    #pragma unroll
    for (int i = 0; i < 4; ++i)
        #pragma unroll
        for (int j = 0; j < 8; ++j) acc[i][j] = 0.0f;
    gemm_acc<8>(acc, W_o1, HID, HID, 8, As_x, HID, Wst, tid, c, rg4);
    #pragma unroll
    for (int j = 0; j < 8; ++j) {
        int n = c + 32 * j;
        float b = b_o1[n];
        #pragma unroll
        for (int i = 0; i < 4; ++i)
            As_h[(rg4 + i) * HID + n] = fmaxf(acc[i][j] + b, 0.0f);
    }
    __syncthreads();

    // ---- P6: z_next = y @ W_o2^T + b_o2 (N = 64) ----
    float acc2[4][2];
    #pragma unroll
    for (int i = 0; i < 4; ++i) { acc2[i][0] = 0.0f; acc2[i][1] = 0.0f; }
    gemm_acc<2>(acc2, W_o2, HID, HID, 8, As_h, HID, Wst, tid, c, rg4);
    #pragma unroll
    for (int j = 0; j < 2; ++j) {
        int n = c + 32 * j;
        float b = b_o2[n];
        #pragma unroll
        for (int i = 0; i < 4; ++i)
            out_z[(row0 + rg4 + i) * LATENT + n] = acc2[i][j] + b;
    }
}

extern "C" void kernel_launch(void* const* d_in, const int* in_sizes, int n_in,
                              void* d_out, int out_size) {
    const float* z      = (const float*)d_in[0];
    const float* action = (const float*)d_in[1];
    const float* hidden = (const float*)d_in[2];
    const float* W_in   = (const float*)d_in[3];
    const float* b_in   = (const float*)d_in[4];
    const float* W_ih   = (const float*)d_in[5];
    const float* W_hh   = (const float*)d_in[6];
    const float* b_ih   = (const float*)d_in[7];
    const float* b_hh   = (const float*)d_in[8];
    const float* W_o1   = (const float*)d_in[9];
    const float* b_o1   = (const float*)d_in[10];
    const float* W_o2   = (const float*)d_in[11];
    const float* b_o2   = (const float*)d_in[12];

    const int B = in_sizes[0] / LATENT;   // 131072
    float* out_z = (float*)d_out;                      // [B, 64]
    float* out_h = (float*)d_out + (long)B * LATENT;   // [B, 256]

    const int smem_bytes = (3 * TM * HID + TM * ZA_LD + 32 * WST_LD) * sizeof(float);
    static bool attr_set = false;
    // idempotent, not an allocation, executes immediately (not captured)
    cudaFuncSetAttribute(latent_dynamics_kernel,
                         cudaFuncAttributeMaxDynamicSharedMemorySize, smem_bytes);
    (void)attr_set;

    dim3 grid(B / TM);
    latent_dynamics_kernel<<<grid, THREADS, smem_bytes>>>(
        z, action, hidden, W_in, b_in, W_ih, W_hh, b_ih, b_hh,
        W_o1, b_o1, W_o2, b_o2, out_z, out_h);
}